// round 1
// baseline (speedup 1.0000x reference)
#include <cuda_runtime.h>

#define NB 2
#define NA 100000
#define NC 80
#define NCLS 79          // classes excluding background (class 0)
#define KPERF 500
#define KPROP 100
#define NTASK (NB*NCLS)  // 158
#define SCORE_THR 0.05f
#define CAP 2048

typedef unsigned long long u64;
typedef unsigned int u32;

// scratch (static device arrays: allocation-free per harness rules)
__device__ float  g_scoresT[(size_t)NB*NC*NA];   // 64 MB transposed scores [B,C,A]
__device__ float4 g_boxesDec[NB*NA];             // decoded, clipped boxes
__device__ float  g_vals[NTASK*KPERF];           // post-NMS per-class vals (-1 if dropped)
__device__ int    g_aidx[NTASK*KPERF];           // anchor indices per slot

__device__ __forceinline__ u32 fmono(float f){
    u32 u = __float_as_uint(f);
    return (u & 0x80000000u) ? ~u : (u | 0x80000000u);
}
__device__ __forceinline__ float fmono_inv(u32 k){
    return __uint_as_float((k & 0x80000000u) ? (k & 0x7FFFFFFFu) : ~k);
}

// ---------------------------------------------------------------- decode
__global__ void decode_kernel(const float* __restrict__ bbox,
                              const float* __restrict__ anchors){
    int i = blockIdx.x*blockDim.x + threadIdx.x;
    if (i >= NB*NA) return;
    int a = i % NA;
    float4 d  = reinterpret_cast<const float4*>(bbox)[i];
    float4 an = reinterpret_cast<const float4*>(anchors)[a];
    const float MAXR = 4.135166556742356f;   // |ln(16/1000)|
    float dw = fminf(fmaxf(d.z, -MAXR), MAXR);
    float dh = fminf(fmaxf(d.w, -MAXR), MAXR);
    float pw = an.z - an.x, ph = an.w - an.y;
    float px = (an.x + an.z)*0.5f, py = (an.y + an.w)*0.5f;
    float gw = pw*expf(dw), gh = ph*expf(dh);
    float gx = px + pw*d.x, gy = py + ph*d.y;
    float4 o;
    o.x = fminf(fmaxf(gx - gw*0.5f, 0.f), 1.f);
    o.y = fminf(fmaxf(gy - gh*0.5f, 0.f), 1.f);
    o.z = fminf(fmaxf(gx + gw*0.5f, 0.f), 1.f);
    o.w = fminf(fmaxf(gy + gh*0.5f, 0.f), 1.f);
    g_boxesDec[i] = o;
}

// ---------------------------------------------------------------- transpose [B,A,C] -> [B,C,A]
__global__ void transpose_kernel(const float* __restrict__ y){
    __shared__ float tile[32][33];
    int b  = blockIdx.z;
    int a0 = blockIdx.x*32, c0 = blockIdx.y*32;
    int tx = threadIdx.x, ty = threadIdx.y;     // 32 x 8
    #pragma unroll
    for (int r = 0; r < 32; r += 8){
        int a = a0 + ty + r, c = c0 + tx;
        if (c < NC) tile[ty+r][tx] = y[((size_t)b*NA + a)*NC + c];
    }
    __syncthreads();
    #pragma unroll
    for (int r = 0; r < 32; r += 8){
        int c = c0 + ty + r, a = a0 + tx;
        if (c < NC) g_scoresT[((size_t)b*NC + c)*NA + a] = tile[tx][ty+r];
    }
}

// ---------------------------------------------------------------- cutoff via parallel suffix-scan (512 thr, 4096 bins)
__device__ void find_cutoff_4096(int* hist, int* part, int K, int* c_out, int* above_out){
    int tid = threadIdx.x;
    int p = 0;
    #pragma unroll
    for (int k = 0; k < 8; k++) p += hist[tid*8 + k];
    part[tid] = p;
    __syncthreads();
    for (int off = 1; off < 512; off <<= 1){
        int v = part[tid];
        if (tid + off < 512) v += part[tid + off];
        __syncthreads();
        part[tid] = v;
        __syncthreads();
    }
    if (tid == 0 && part[0] < K){ *c_out = 0; *above_out = 0; }
    if (part[tid] >= K && (tid == 511 || part[tid+1] < K)){
        int cum = (tid == 511) ? 0 : part[tid+1];
        for (int bin = tid*8 + 7; bin >= tid*8; bin--){
            cum += hist[bin];
            if (cum >= K){ *c_out = bin; *above_out = cum - hist[bin]; break; }
        }
    }
    __syncthreads();
}

// ---------------------------------------------------------------- bitonic (descending), n = pow2
__device__ void bitonic_sort_desc(u64* d, int n){
    int tid = threadIdx.x, nt = blockDim.x;
    for (int k = 2; k <= n; k <<= 1)
        for (int j = k >> 1; j > 0; j >>= 1){
            for (int i = tid; i < n; i += nt){
                int ixj = i ^ j;
                if (ixj > i){
                    u64 a = d[i], b = d[ixj];
                    bool descRegion = ((i & k) == 0);
                    if (descRegion ? (a < b) : (a > b)){ d[i] = b; d[ixj] = a; }
                }
            }
            __syncthreads();
        }
}

// ---------------------------------------------------------------- per (image,class): top-500 + greedy NMS
__global__ __launch_bounds__(512) void nms_kernel(){
    __shared__ __align__(16) unsigned char arena[32768];
    int* hist  = (int*)arena;                    // 4096 ints (select phase)
    u64* sbuf  = (u64*)(arena + 16384);          // 2048 u64  (select phase)
    u32* masks = (u32*)arena;                    // 500*16 u32 (NMS phase, reuses arena)
    __shared__ int part[512];
    __shared__ float  svals[KPERF];
    __shared__ int    saidx[KPERF];
    __shared__ float4 sboxes[KPERF];
    __shared__ int sc1, sab1, sc2, sab2, scnt;

    int tid = threadIdx.x;
    int t = blockIdx.x;
    int b = t / NCLS, cls = 1 + (t % NCLS);
    const float* col = g_scoresT + ((size_t)b*NC + cls)*NA;

    // ---- level-1 histogram on value bins
    for (int i = tid; i < 4096; i += 512) hist[i] = 0;
    __syncthreads();
    for (int a = tid; a < NA; a += 512){
        float v = col[a];
        if (v > SCORE_THR){
            int bin = (int)(v*4096.0f); bin = max(0, min(4095, bin));
            atomicAdd(&hist[bin], 1);
        }
    }
    __syncthreads();
    find_cutoff_4096(hist, part, KPERF, &sc1, &sab1);
    int c1 = sc1, ab1 = sab1;

    // ---- level-2 sub-histogram inside cutoff bin
    for (int i = tid; i < 4096; i += 512) hist[i] = 0;
    __syncthreads();
    for (int a = tid; a < NA; a += 512){
        float v = col[a];
        if (v > SCORE_THR){
            float t1 = v*4096.0f;
            int bin = (int)t1; bin = max(0, min(4095, bin));
            if (bin == c1){
                float fr = t1 - (float)c1;
                int sub = (int)(fr*4096.0f); sub = max(0, min(4095, sub));
                atomicAdd(&hist[sub], 1);
            }
        }
    }
    __syncthreads();
    find_cutoff_4096(hist, part, KPERF - ab1, &sc2, &sab2);
    int c2 = sc2;

    // ---- gather candidates >= cutoff
    if (tid == 0) scnt = 0;
    __syncthreads();
    for (int a = tid; a < NA; a += 512){
        float v = col[a];
        if (v > SCORE_THR){
            float t1 = v*4096.0f;
            int bin = (int)t1; bin = max(0, min(4095, bin));
            bool sel = bin > c1;
            if (bin == c1){
                float fr = t1 - (float)c1;
                int sub = (int)(fr*4096.0f); sub = max(0, min(4095, sub));
                sel = (sub >= c2);
            }
            if (sel){
                int p = atomicAdd(&scnt, 1);
                if (p < CAP) sbuf[p] = ((u64)fmono(v) << 32) | (u64)(0xFFFFFFFFu - (u32)a);
            }
        }
    }
    __syncthreads();
    int n = min(scnt, CAP);
    for (int i = n + tid; i < CAP; i += 512) sbuf[i] = 0ull;
    __syncthreads();

    // ---- exact sort: key desc, anchor idx asc on ties (matches lax.top_k)
    bitonic_sort_desc(sbuf, CAP);

    if (tid < KPERF){
        u64 key = sbuf[tid];
        u32 mk = (u32)(key >> 32);
        if (mk > 0x80000000u){
            svals[tid] = fmono_inv(mk);
            saidx[tid] = (int)(0xFFFFFFFFu - (u32)key);
        } else { svals[tid] = -1.0f; saidx[tid] = 0; }
    }
    __syncthreads();
    if (tid < KPERF) sboxes[tid] = g_boxesDec[b*NA + saidx[tid]];
    __syncthreads();

    // ---- IOU bitmask matrix (arena reused; sbuf reads are done)
    if (tid < KPERF){
        float4 bi = sboxes[tid];
        float areai = (bi.z - bi.x)*(bi.w - bi.y);
        for (int w = 0; w < 16; w++){
            u32 bits = 0;
            int jmax = min(32, KPERF - w*32);
            for (int j2 = 0; j2 < jmax; j2++){
                float4 bj = sboxes[w*32 + j2];
                float lx = fmaxf(bi.x, bj.x), ly = fmaxf(bi.y, bj.y);
                float rx = fminf(bi.z, bj.z), ry = fminf(bi.w, bj.w);
                float iw = fmaxf(rx - lx, 0.f), ih = fmaxf(ry - ly, 0.f);
                float inter = iw*ih;
                float uni = areai + (bj.z - bj.x)*(bj.w - bj.y) - inter;
                float iou = inter / fmaxf(uni, 1e-9f);
                if (iou > 0.5f) bits |= (1u << j2);
            }
            masks[tid*16 + w] = bits;
        }
    }
    __syncthreads();

    // ---- greedy scan: warp 0, removed bitset resident in lanes 0..15
    if (tid < 32){
        u32 rem = 0;
        for (int i = 0; i < KPERF; i++){
            u32 rw = __shfl_sync(0xFFFFFFFFu, rem, i >> 5);
            bool sup = (rw >> (i & 31)) & 1u;
            bool keep = (svals[i] > 0.0f) && !sup;
            if (keep){
                if (tid < 16) rem |= masks[i*16 + tid];
            } else {
                if (tid == 0) svals[i] = -1.0f;
            }
        }
    }
    __syncthreads();
    for (int i = tid; i < KPERF; i += 512){
        g_vals[t*KPERF + i] = svals[i];
        g_aidx[t*KPERF + i] = saidx[i];
    }
}

// ---------------------------------------------------------------- per image: global top-100 + output gather
__global__ __launch_bounds__(512) void final_kernel(const float* __restrict__ y_pred,
                                                    float* __restrict__ out){
    __shared__ int hist[4096];
    __shared__ int part[512];
    __shared__ u64 sbuf[512];
    __shared__ int sc1, sab1, sc2, sab2, scnt;
    __shared__ int sA[KPROP];
    int tid = threadIdx.x;
    int b = blockIdx.x;
    const int N = NCLS*KPERF;                    // 39500, flat order = (class,rank)
    const float* vals = g_vals + b*N;

    for (int i = tid; i < 4096; i += 512) hist[i] = 0;
    __syncthreads();
    for (int i = tid; i < N; i += 512){
        float v = vals[i];
        if (v > 0.f){ int bin = (int)(v*4096.f); bin = max(0, min(4095, bin)); atomicAdd(&hist[bin], 1); }
    }
    __syncthreads();
    find_cutoff_4096(hist, part, KPROP, &sc1, &sab1);
    int c1 = sc1, ab1 = sab1;

    for (int i = tid; i < 4096; i += 512) hist[i] = 0;
    __syncthreads();
    for (int i = tid; i < N; i += 512){
        float v = vals[i];
        if (v > 0.f){
            float t1 = v*4096.f; int bin = (int)t1; bin = max(0, min(4095, bin));
            if (bin == c1){
                float fr = t1 - (float)c1;
                int sub = (int)(fr*4096.f); sub = max(0, min(4095, sub));
                atomicAdd(&hist[sub], 1);
            }
        }
    }
    __syncthreads();
    find_cutoff_4096(hist, part, KPROP - ab1, &sc2, &sab2);
    int c2 = sc2;

    if (tid == 0) scnt = 0;
    __syncthreads();
    for (int i = tid; i < N; i += 512){
        float v = vals[i];
        if (v > 0.f){
            float t1 = v*4096.f; int bin = (int)t1; bin = max(0, min(4095, bin));
            bool sel = bin > c1;
            if (bin == c1){
                float fr = t1 - (float)c1;
                int sub = (int)(fr*4096.f); sub = max(0, min(4095, sub));
                sel = (sub >= c2);
            }
            if (sel){
                int p = atomicAdd(&scnt, 1);
                if (p < 512) sbuf[p] = ((u64)fmono(v) << 32) | (u64)(0xFFFFFFFFu - (u32)i);
            }
        }
    }
    __syncthreads();
    int n = min(scnt, 512);
    for (int i = n + tid; i < 512; i += 512) sbuf[i] = 0ull;
    __syncthreads();
    bitonic_sort_desc(sbuf, 512);

    if (tid < KPROP){
        u64 key = sbuf[tid];
        u32 mk = (u32)(key >> 32);
        if (mk > 0x80000000u){
            int flat = (int)(0xFFFFFFFFu - (u32)key);
            sA[tid] = g_aidx[b*N + flat];
        } else sA[tid] = -1;                      // invalid -> zero rows
    }
    __syncthreads();

    float* oscores = out;                         // [B,PROP,C]
    float* oboxes  = out + NB*KPROP*NC;           // [B,PROP,4]
    for (int idx = tid; idx < KPROP*NC; idx += 512){
        int p = idx / NC, c = idx % NC;
        int a = sA[p];
        oscores[(b*KPROP + p)*NC + c] = (a >= 0) ? y_pred[((size_t)b*NA + a)*NC + c] : 0.f;
    }
    if (tid < KPROP){
        int a = sA[tid];
        float4 bx = (a >= 0) ? g_boxesDec[b*NA + a] : make_float4(0.f, 0.f, 0.f, 0.f);
        reinterpret_cast<float4*>(oboxes)[b*KPROP + tid] = bx;
    }
}

// ----------------------------------------------------------------
extern "C" void kernel_launch(void* const* d_in, const int* in_sizes, int n_in,
                              void* d_out, int out_size){
    (void)in_sizes; (void)n_in; (void)out_size;
    const float* y    = (const float*)d_in[0];   // [B,A,C]
    const float* bbox = (const float*)d_in[1];   // [B,A,4]
    const float* anch = (const float*)d_in[2];   // [A,4]
    float* out = (float*)d_out;

    decode_kernel<<<(NB*NA + 255)/256, 256>>>(bbox, anch);
    transpose_kernel<<<dim3(NA/32, (NC + 31)/32, NB), dim3(32, 8)>>>(y);
    nms_kernel<<<NTASK, 512>>>();
    final_kernel<<<NB, 512>>>(y, out);
}

// round 3
// speedup vs baseline: 1.5524x; 1.5524x over previous
#include <cuda_runtime.h>

#define NB 2
#define NA 100000
#define NC 80
#define NCLS 79          // classes excluding background (class 0)
#define KPERF 500
#define KPROP 100
#define NTASK (NB*NCLS)  // 158
#define SCORE_THR 0.05f
#define HB 128           // coarse bins for per-class cutoff
#define CAP 4096         // per-class candidate capacity
#define NSLAB 74
#define CHUNK 1352       // ceil(NA/NSLAB)
#define KEEPC 128        // kept entries per class forwarded to final

typedef unsigned long long u64;
typedef unsigned int u32;

// ---- scratch (static device arrays; allocation-free) ----
__device__ float4 g_boxesDec[NB*NA];
__device__ int    g_hist[NTASK*HB];
__device__ int    g_c1[NTASK];
__device__ int    g_cnt[NTASK];
__device__ u64    g_cand[(size_t)NTASK*CAP];   // 5.2 MB
__device__ float  g_fval[NTASK*KEEPC];
__device__ int    g_fflat[NTASK*KEEPC];
__device__ int    g_faidx[NTASK*KEEPC];

__device__ __forceinline__ u32 fmono(float f){
    u32 u = __float_as_uint(f);
    return (u & 0x80000000u) ? ~u : (u | 0x80000000u);
}
__device__ __forceinline__ float fmono_inv(u32 k){
    return __uint_as_float((k & 0x80000000u) ? (k & 0x7FFFFFFFu) : ~k);
}
__device__ __forceinline__ int bin128(float v){
    int b = (int)(v * 128.0f);
    return b > 127 ? 127 : b;
}

// ---------------------------------------------------------------- zero scratch
__global__ void zero_kernel(){
    int i = blockIdx.x*blockDim.x + threadIdx.x;
    int n = NTASK*HB;
    for (int k = i; k < n; k += gridDim.x*blockDim.x) g_hist[k] = 0;
    if (i < NTASK) g_cnt[i] = 0;
}

// ---------------------------------------------------------------- decode boxes
__global__ void decode_kernel(const float* __restrict__ bbox,
                              const float* __restrict__ anchors){
    int i = blockIdx.x*blockDim.x + threadIdx.x;
    if (i >= NB*NA) return;
    int a = i % NA;
    float4 d  = reinterpret_cast<const float4*>(bbox)[i];
    float4 an = reinterpret_cast<const float4*>(anchors)[a];
    const float MAXR = 4.135166556742356f;   // |ln(16/1000)|
    float dw = fminf(fmaxf(d.z, -MAXR), MAXR);
    float dh = fminf(fmaxf(d.w, -MAXR), MAXR);
    float pw = an.z - an.x, ph = an.w - an.y;
    float px = (an.x + an.z)*0.5f, py = (an.y + an.w)*0.5f;
    float gw = pw*expf(dw), gh = ph*expf(dh);
    float gx = px + pw*d.x, gy = py + ph*d.y;
    float4 o;
    o.x = fminf(fmaxf(gx - gw*0.5f, 0.f), 1.f);
    o.y = fminf(fmaxf(gy - gh*0.5f, 0.f), 1.f);
    o.z = fminf(fmaxf(gx + gw*0.5f, 0.f), 1.f);
    o.w = fminf(fmaxf(gy + gh*0.5f, 0.f), 1.f);
    g_boxesDec[i] = o;
}

// ---------------------------------------------------------------- pass A: per-class 128-bin histograms
// 640 = 32 anchors x 20 float4-lanes; each thread owns a fixed class quartet.
__global__ __launch_bounds__(640) void passA_kernel(const float* __restrict__ y){
    __shared__ int sh[NCLS*HB];          // 79*128*4 = 40448 B
    int tid = threadIdx.x;
    int b = blockIdx.y, s = blockIdx.x;
    for (int i = tid; i < NCLS*HB; i += 640) sh[i] = 0;
    __syncthreads();

    int a0 = s*CHUNK;
    int aN = min(CHUNK, NA - a0);
    const float4* base = reinterpret_cast<const float4*>(y + ((size_t)b*NA + a0)*NC);
    int p  = tid % 20;
    int c0 = p*4;
    int nf4 = aN*20;
    for (int j = tid; j < nf4; j += 640){
        float4 v = base[j];
        if (c0 != 0 && v.x > SCORE_THR) atomicAdd(&sh[(c0-1)*HB + bin128(v.x)], 1);
        if (v.y > SCORE_THR) atomicAdd(&sh[(c0  )*HB + bin128(v.y)], 1);
        if (v.z > SCORE_THR) atomicAdd(&sh[(c0+1)*HB + bin128(v.z)], 1);
        if (v.w > SCORE_THR) atomicAdd(&sh[(c0+2)*HB + bin128(v.w)], 1);
    }
    __syncthreads();
    int tb = b*NCLS*HB;
    for (int i = tid; i < NCLS*HB; i += 640)
        if (sh[i]) atomicAdd(&g_hist[tb + i], sh[i]);
}

// ---------------------------------------------------------------- per-class cutoff bin
__global__ void cutoff_kernel(){
    __shared__ int sh[HB];
    __shared__ int c1s;
    int t = blockIdx.x, tid = threadIdx.x;
    sh[tid] = g_hist[t*HB + tid];
    __syncthreads();
    for (int off = 1; off < HB; off <<= 1){
        int v = sh[tid];
        if (tid + off < HB) v += sh[tid + off];
        __syncthreads();
        sh[tid] = v;
        __syncthreads();
    }
    if (tid == 0) c1s = 0;
    __syncthreads();
    if (sh[tid] >= KPERF && (tid == HB-1 || sh[tid+1] < KPERF)) c1s = tid;
    __syncthreads();
    if (tid == 0) g_c1[t] = (sh[0] < KPERF) ? 0 : c1s;
}

// ---------------------------------------------------------------- pass B: compact candidates
__global__ __launch_bounds__(640) void passB_kernel(const float* __restrict__ y){
    int tid = threadIdx.x;
    int b = blockIdx.y, s = blockIdx.x;
    int p  = tid % 20;
    int c0 = p*4;
    // per-thread class thresholds (bin units) and task ids, in registers
    int t0 = b*NCLS + (c0-1), t1 = b*NCLS + c0, t2 = b*NCLS + c0+1, t3 = b*NCLS + c0+2;
    float l0 = (c0 == 0) ? 1e30f : (float)g_c1[t0];
    float l1 = (float)g_c1[t1];
    float l2 = (float)g_c1[t2];
    float l3 = (float)g_c1[t3];

    int a0 = s*CHUNK;
    int aN = min(CHUNK, NA - a0);
    const float4* base = reinterpret_cast<const float4*>(y + ((size_t)b*NA + a0)*NC);
    int arow = tid / 20;
    int nf4 = aN*20;
    int k = 0;
    for (int j = tid; j < nf4; j += 640, k++){
        float4 v = base[j];
        u32 a = (u32)(a0 + arow + k*32);
        u64 alo = (u64)(0xFFFFFFFFu - a);
        if (c0 != 0 && v.x > SCORE_THR && v.x*128.0f >= l0){
            int pos = atomicAdd(&g_cnt[t0], 1);
            if (pos < CAP) g_cand[(size_t)t0*CAP + pos] = ((u64)fmono(v.x) << 32) | alo;
        }
        if (v.y > SCORE_THR && v.y*128.0f >= l1){
            int pos = atomicAdd(&g_cnt[t1], 1);
            if (pos < CAP) g_cand[(size_t)t1*CAP + pos] = ((u64)fmono(v.y) << 32) | alo;
        }
        if (v.z > SCORE_THR && v.z*128.0f >= l2){
            int pos = atomicAdd(&g_cnt[t2], 1);
            if (pos < CAP) g_cand[(size_t)t2*CAP + pos] = ((u64)fmono(v.z) << 32) | alo;
        }
        if (v.w > SCORE_THR && v.w*128.0f >= l3){
            int pos = atomicAdd(&g_cnt[t3], 1);
            if (pos < CAP) g_cand[(size_t)t3*CAP + pos] = ((u64)fmono(v.w) << 32) | alo;
        }
    }
}

// ---------------------------------------------------------------- bitonic (descending), n = pow2
__device__ void bitonic_sort_desc(u64* d, int n){
    int tid = threadIdx.x, nt = blockDim.x;
    for (int k = 2; k <= n; k <<= 1)
        for (int j = k >> 1; j > 0; j >>= 1){
            for (int i = tid; i < n; i += nt){
                int ixj = i ^ j;
                if (ixj > i){
                    u64 a = d[i], b = d[ixj];
                    bool descRegion = ((i & k) == 0);
                    if (descRegion ? (a < b) : (a > b)){ d[i] = b; d[ixj] = a; }
                }
            }
            __syncthreads();
        }
}

// ---------------------------------------------------------------- per (image,class): sort + NMS + compact kept
__global__ __launch_bounds__(512) void nms_kernel(){
    __shared__ u64 sbuf[CAP];            // 32 KB; aliased as masks after extraction
    __shared__ float4 sboxes[KPERF];
    __shared__ float  svals[KPERF];
    __shared__ int    saidx[KPERF];
    __shared__ u32 validw[16], alivew[16];
    __shared__ int wpref[16];
    u32* masks = (u32*)sbuf;             // 500*16 u32 = 32000 B

    int tid = threadIdx.x;
    int t = blockIdx.x;
    int clsr = t % NCLS;

    // init output region
    for (int kk = tid; kk < KEEPC; kk += 512) g_fval[t*KEEPC + kk] = -1.0f;

    int n = min(g_cnt[t], CAP);
    int n2 = 512;
    while (n2 < n) n2 <<= 1;
    for (int i = tid; i < n2; i += 512)
        sbuf[i] = (i < n) ? g_cand[(size_t)t*CAP + i] : 0ull;
    __syncthreads();

    bitonic_sort_desc(sbuf, n2);

    if (tid < KPERF){
        u64 key = sbuf[tid];
        u32 mk = (u32)(key >> 32);
        if (mk > 0x80000000u){
            svals[tid] = fmono_inv(mk);
            saidx[tid] = (int)(0xFFFFFFFFu - (u32)key);
        } else { svals[tid] = -1.0f; saidx[tid] = 0; }
    }
    __syncthreads();
    if (tid < KPERF) sboxes[tid] = g_boxesDec[(t/NCLS)*NA + saidx[tid]];
    __syncthreads();   // sbuf reads complete; safe to alias as masks

    // ---- triangle IOU bitmask (bits only for j > i)
    if (tid < KPERF){
        float4 bi = sboxes[tid];
        float areai = (bi.z - bi.x)*(bi.w - bi.y);
        int w0 = tid >> 5;
        for (int w = 0; w < w0; w++) masks[tid*16 + w] = 0u;
        for (int w = w0; w < 16; w++){
            u32 bits = 0;
            int jbase = w*32;
            int j2s = (w == w0) ? (tid & 31) + 1 : 0;
            int jmax = min(32, KPERF - jbase);
            for (int j2 = j2s; j2 < jmax; j2++){
                float4 bj = sboxes[jbase + j2];
                float lx = fmaxf(bi.x, bj.x), ly = fmaxf(bi.y, bj.y);
                float rx = fminf(bi.z, bj.z), ry = fminf(bi.w, bj.w);
                float iw = fmaxf(rx - lx, 0.f), ih = fmaxf(ry - ly, 0.f);
                float inter = iw*ih;
                float uni = areai + (bj.z - bj.x)*(bj.w - bj.y) - inter;
                float iou = inter / fmaxf(uni, 1e-9f);
                if (iou > 0.5f) bits |= (1u << j2);
            }
            masks[tid*16 + w] = bits;
        }
    }
    // valid bitset via ballot
    {
        u32 bal = __ballot_sync(0xFFFFFFFFu, tid < KPERF && svals[tid] > 0.0f);
        if ((tid & 31) == 0) validw[tid >> 5] = bal;
    }
    __syncthreads();

    // ---- greedy scan (warp 0): alive bitset in lanes 0..15, prefetched mask rows
    if (tid < 32){
        u32 alive = (tid < 16) ? validw[tid] : 0u;
        u32 m = (tid < 16) ? masks[tid] : 0u;          // row 0
        for (int i = 0; i < KPERF; i++){
            u32 mn = (tid < 16 && i+1 < KPERF) ? masks[(i+1)*16 + tid] : 0u;
            u32 a = __shfl_sync(0xFFFFFFFFu, alive, i >> 5);
            if ((a >> (i & 31)) & 1u) alive &= ~m;
            m = mn;
        }
        if (tid < 16) alivew[tid] = alive;
    }
    __syncthreads();
    if (tid == 0){
        int acc = 0;
        #pragma unroll
        for (int w = 0; w < 16; w++){ wpref[w] = acc; acc += __popc(alivew[w]); }
    }
    __syncthreads();

    // ---- compact first KEEPC kept entries
    if (tid < KPERF){
        int w = tid >> 5, b2 = tid & 31;
        if ((alivew[w] >> b2) & 1u){
            int rank = wpref[w] + __popc(alivew[w] & ((1u << b2) - 1u));
            if (rank < KEEPC){
                g_fval [t*KEEPC + rank] = svals[tid];
                g_fflat[t*KEEPC + rank] = clsr*KPERF + tid;
                g_faidx[t*KEEPC + rank] = saidx[tid];
            }
        }
    }
}

// ---------------------------------------------------------------- cutoff helper (4096 bins, 512 thr)
// returns cutoff bin *c_out and count strictly above it *above_out
__device__ void find_cutoff_4096(int* hist, int* part, int K, int* c_out, int* above_out){
    int tid = threadIdx.x;
    int p = 0;
    #pragma unroll
    for (int k = 0; k < 8; k++) p += hist[tid*8 + k];
    part[tid] = p;
    __syncthreads();
    for (int off = 1; off < 512; off <<= 1){
        int v = part[tid];
        if (tid + off < 512) v += part[tid + off];
        __syncthreads();
        part[tid] = v;
        __syncthreads();
    }
    if (tid == 0 && part[0] < K){ *c_out = 0; *above_out = 0; }
    if (part[tid] >= K && (tid == 511 || part[tid+1] < K)){
        int cum = (tid == 511) ? 0 : part[tid+1];
        for (int bn = tid*8 + 7; bn >= tid*8; bn--){
            cum += hist[bn];
            if (cum >= K){ *c_out = bn; *above_out = cum - hist[bn]; break; }
        }
    }
    __syncthreads();
}

// ---------------------------------------------------------------- per image: global top-100 + gather
// TWO-LEVEL cutoff: kept values concentrate in the top few coarse bins (all per-class
// candidates are >= ~0.992), so a single 4096-bin level leaves >>512 in the cutoff
// bin.  Level 2 sub-bins the cutoff bin at 1/16.7M resolution.
__global__ __launch_bounds__(512) void final_kernel(const float* __restrict__ y_pred,
                                                    float* __restrict__ out){
    __shared__ int hist[4096];
    __shared__ int part[512];
    __shared__ u64 skey[512];
    __shared__ int sc1, sab1, sc2, sab2, scnt;
    __shared__ int sA[KPROP];
    int tid = threadIdx.x;
    int b = blockIdx.x;
    const int M = NCLS*KEEPC;                  // 10112
    const int gbase = b*M;

    // ---- level 1
    for (int i = tid; i < 4096; i += 512) hist[i] = 0;
    __syncthreads();
    for (int i = tid; i < M; i += 512){
        float v = g_fval[gbase + i];
        if (v > 0.f){
            int bn = (int)(v*4096.f); bn = bn > 4095 ? 4095 : bn;
            atomicAdd(&hist[bn], 1);
        }
    }
    __syncthreads();
    find_cutoff_4096(hist, part, KPROP, &sc1, &sab1);
    int c1 = sc1, ab1 = sab1;

    // ---- level 2: sub-histogram inside cutoff bin c1
    for (int i = tid; i < 4096; i += 512) hist[i] = 0;
    __syncthreads();
    for (int i = tid; i < M; i += 512){
        float v = g_fval[gbase + i];
        if (v > 0.f){
            float t1 = v*4096.f;
            int bn = (int)t1; bn = bn > 4095 ? 4095 : bn;
            if (bn == c1){
                float fr = t1 - (float)c1;
                int sub = (int)(fr*4096.f); sub = sub < 0 ? 0 : (sub > 4095 ? 4095 : sub);
                atomicAdd(&hist[sub], 1);
            }
        }
    }
    __syncthreads();
    find_cutoff_4096(hist, part, KPROP - ab1, &sc2, &sab2);
    int c2 = sc2;

    // ---- gather survivors (bin > c1, or bin == c1 && sub >= c2)
    if (tid == 0) scnt = 0;
    __syncthreads();
    for (int i = tid; i < M; i += 512){
        float v = g_fval[gbase + i];
        if (v > 0.f){
            float t1 = v*4096.f;
            int bn = (int)t1; bn = bn > 4095 ? 4095 : bn;
            bool sel = bn > c1;
            if (bn == c1){
                float fr = t1 - (float)c1;
                int sub = (int)(fr*4096.f); sub = sub < 0 ? 0 : (sub > 4095 ? 4095 : sub);
                sel = (sub >= c2);
            }
            if (sel){
                int pos = atomicAdd(&scnt, 1);
                if (pos < 512){
                    u32 fflat = (u32)g_fflat[gbase + i];
                    skey[pos] = ((u64)fmono(v) << 32) | ((u64)(65535u - fflat) << 14) | (u64)i;
                }
            }
        }
    }
    __syncthreads();
    int n = min(scnt, 512);
    for (int i = n + tid; i < 512; i += 512) skey[i] = 0ull;
    __syncthreads();
    bitonic_sort_desc(skey, 512);

    if (tid < KPROP){
        u64 key = skey[tid];
        u32 mk = (u32)(key >> 32);
        if (mk > 0x80000000u){
            int slot = (int)(key & 0x3FFFull);
            sA[tid] = g_faidx[gbase + slot];
        } else sA[tid] = -1;
    }
    __syncthreads();

    float* oscores = out;                         // [B,PROP,C]
    float* oboxes  = out + NB*KPROP*NC;           // [B,PROP,4]
    for (int idx = tid; idx < KPROP*NC; idx += 512){
        int p = idx / NC, c = idx % NC;
        int a = sA[p];
        oscores[(b*KPROP + p)*NC + c] = (a >= 0) ? y_pred[((size_t)b*NA + a)*NC + c] : 0.f;
    }
    if (tid < KPROP){
        int a = sA[tid];
        float4 bx = (a >= 0) ? g_boxesDec[b*NA + a] : make_float4(0.f, 0.f, 0.f, 0.f);
        reinterpret_cast<float4*>(oboxes)[b*KPROP + tid] = bx;
    }
}

// ----------------------------------------------------------------
extern "C" void kernel_launch(void* const* d_in, const int* in_sizes, int n_in,
                              void* d_out, int out_size){
    (void)in_sizes; (void)n_in; (void)out_size;
    const float* y    = (const float*)d_in[0];   // [B,A,C]
    const float* bbox = (const float*)d_in[1];   // [B,A,4]
    const float* anch = (const float*)d_in[2];   // [A,4]
    float* out = (float*)d_out;

    zero_kernel<<<80, 256>>>();
    decode_kernel<<<(NB*NA + 255)/256, 256>>>(bbox, anch);
    passA_kernel<<<dim3(NSLAB, NB), 640>>>(y);
    cutoff_kernel<<<NTASK, HB>>>();
    passB_kernel<<<dim3(NSLAB, NB), 640>>>(y);
    nms_kernel<<<NTASK, 512>>>();
    final_kernel<<<NB, 512>>>(y, out);
}